// round 1
// baseline (speedup 1.0000x reference)
#include <cuda_runtime.h>
#include <math.h>

#define H 1024
#define I 2048
#define E 8
#define TOPK 2
#define T 4096   // B*S = 2*2048

// ---------------- scratch (static device globals; no allocation) -------------
__device__ __align__(256) int   g_counts[E];
__device__ __align__(256) float g_probsum[E];
__device__ float g_zsum;
__device__ __align__(256) int   g_list[E * T];
__device__ __align__(256) float g_wlist[E * T];
// activation scratch: slot-major per expert; slot e==E is the shared expert
__device__ __align__(256) float g_act[(size_t)(E + 1) * T * I];

// ---------------- init ------------------------------------------------------
__global__ void init_kernel() {
    int i = threadIdx.x;
    if (i < E) { g_counts[i] = 0; g_probsum[i] = 0.f; }
    if (i == 0) g_zsum = 0.f;
}

// ---------------- router: 1 warp per token ----------------------------------
__global__ void router_kernel(const float* __restrict__ x,
                              const float* __restrict__ rw,
                              float* __restrict__ out_logits) {
    int t = blockIdx.x * 8 + (threadIdx.x >> 5);
    int lane = threadIdx.x & 31;
    const float* xr = x + (size_t)t * H;

    float acc[E];
#pragma unroll
    for (int e = 0; e < E; e++) acc[e] = 0.f;

    for (int h = lane; h < H; h += 32) {
        float xv = xr[h];
        const float4* r4 = reinterpret_cast<const float4*>(rw + (size_t)h * E);
        float4 r0 = r4[0];
        float4 r1 = r4[1];
        acc[0] += xv * r0.x; acc[1] += xv * r0.y;
        acc[2] += xv * r0.z; acc[3] += xv * r0.w;
        acc[4] += xv * r1.x; acc[5] += xv * r1.y;
        acc[6] += xv * r1.z; acc[7] += xv * r1.w;
    }
#pragma unroll
    for (int e = 0; e < E; e++) {
#pragma unroll
        for (int off = 16; off > 0; off >>= 1)
            acc[e] += __shfl_xor_sync(0xffffffffu, acc[e], off);
    }

    if (lane == 0) {
        float m = acc[0];
#pragma unroll
        for (int e = 1; e < E; e++) m = fmaxf(m, acc[e]);
        float p[E], s = 0.f;
#pragma unroll
        for (int e = 0; e < E; e++) { p[e] = expf(acc[e] - m); s += p[e]; }
        float inv = 1.f / s;

        // write router_logits
#pragma unroll
        for (int e = 0; e < E; e++) out_logits[(size_t)t * E + e] = acc[e];

        // z-loss partial
        float lse = m + logf(s);
        atomicAdd(&g_zsum, lse * lse);

        // prob-per-expert partials
#pragma unroll
        for (int e = 0; e < E; e++) atomicAdd(&g_probsum[e], p[e] * inv);

        // top-2 (first occurrence on ties, matches jax top_k)
        int e1 = 0;
#pragma unroll
        for (int e = 1; e < E; e++) if (acc[e] > acc[e1]) e1 = e;
        int e2 = (e1 == 0) ? 1 : 0;
#pragma unroll
        for (int e = 0; e < E; e++) if (e != e1 && acc[e] > acc[e2]) e2 = e;

        float p1 = p[e1] * inv, p2 = p[e2] * inv;
        float wn = 1.f / (p1 + p2);

        int pos1 = atomicAdd(&g_counts[e1], 1);
        g_list[e1 * T + pos1]  = t;
        g_wlist[e1 * T + pos1] = p1 * wn;
        int pos2 = atomicAdd(&g_counts[e2], 1);
        g_list[e2 * T + pos2]  = t;
        g_wlist[e2 * T + pos2] = p2 * wn;
    }
}

// ---------------- finalize losses -------------------------------------------
__global__ void finalize_kernel(float* __restrict__ out) {
    if (threadIdx.x == 0) {
        float aux = 0.f;
#pragma unroll
        for (int e = 0; e < E; e++) {
            float tpe = (float)g_counts[e] / (float)(TOPK * T);
            float ppe = g_probsum[e] / (float)T;
            aux += tpe * ppe;
        }
        out[(size_t)T * H]     = (float)E * aux;
        out[(size_t)T * H + 1] = g_zsum / (float)T;
    }
}

// ---------------- GEMM 1: act = silu(X@Wg) * (X@Wu)  -------------------------
// BM=128, BN=64, BK=8, 256 threads, thread-tile 8x4, two accumulator sets.
// blockIdx.z in [0, E]: z<E routed (gathered rows), z==E shared (identity rows)
__global__ void __launch_bounds__(256) gemm_gateup_kernel(
    const float* __restrict__ x,
    const float* __restrict__ gate_w, const float* __restrict__ up_w,
    const float* __restrict__ sgate,  const float* __restrict__ sup) {
    const int e = blockIdx.z;
    int cnt;
    const float *Wg, *Wu;
    if (e < E) {
        cnt = g_counts[e];
        if ((int)blockIdx.y * 128 >= cnt) return;
        Wg = gate_w + (size_t)e * H * I;
        Wu = up_w   + (size_t)e * H * I;
    } else {
        cnt = T;
        Wg = sgate; Wu = sup;
    }

    __shared__ __align__(16) float As[8][128];
    __shared__ __align__(16) float Bg[8][64];
    __shared__ __align__(16) float Bu[8][64];
    __shared__ int rowTok[128];

    const int tid = threadIdx.x;
    const int m0 = blockIdx.y * 128;
    const int n0 = blockIdx.x * 64;

    if (tid < 128) {
        int slot = m0 + tid;
        int tok = -1;
        if (slot < cnt) tok = (e < E) ? g_list[e * T + slot] : slot;
        rowTok[tid] = tok;
    }
    __syncthreads();

    const int la_m = tid >> 1;          // 0..127
    const int la_k = (tid & 1) * 4;     // 0 or 4
    const int lb_k = tid >> 5;          // 0..7
    const int lb_n = (tid & 31) * 2;    // 0..62
    const int ty = tid >> 4;            // 0..15 -> rows ty*8..+7
    const int tx = tid & 15;            // 0..15 -> cols tx*4..+3

    float accg[8][4], accu[8][4];
#pragma unroll
    for (int i = 0; i < 8; i++)
#pragma unroll
        for (int j = 0; j < 4; j++) { accg[i][j] = 0.f; accu[i][j] = 0.f; }

    const int tokA = rowTok[la_m];

    for (int k0 = 0; k0 < H; k0 += 8) {
        float4 av = make_float4(0.f, 0.f, 0.f, 0.f);
        if (tokA >= 0)
            av = *reinterpret_cast<const float4*>(x + (size_t)tokA * H + k0 + la_k);
        As[la_k + 0][la_m] = av.x;
        As[la_k + 1][la_m] = av.y;
        As[la_k + 2][la_m] = av.z;
        As[la_k + 3][la_m] = av.w;

        float2 bgv = *reinterpret_cast<const float2*>(Wg + (size_t)(k0 + lb_k) * I + n0 + lb_n);
        float2 buv = *reinterpret_cast<const float2*>(Wu + (size_t)(k0 + lb_k) * I + n0 + lb_n);
        Bg[lb_k][lb_n]     = bgv.x;
        Bg[lb_k][lb_n + 1] = bgv.y;
        Bu[lb_k][lb_n]     = buv.x;
        Bu[lb_k][lb_n + 1] = buv.y;
        __syncthreads();

#pragma unroll
        for (int k = 0; k < 8; k++) {
            float4 a0 = *reinterpret_cast<const float4*>(&As[k][ty * 8]);
            float4 a1 = *reinterpret_cast<const float4*>(&As[k][ty * 8 + 4]);
            float4 bg = *reinterpret_cast<const float4*>(&Bg[k][tx * 4]);
            float4 bu = *reinterpret_cast<const float4*>(&Bu[k][tx * 4]);
            float a[8]  = {a0.x, a0.y, a0.z, a0.w, a1.x, a1.y, a1.z, a1.w};
            float gb[4] = {bg.x, bg.y, bg.z, bg.w};
            float ub[4] = {bu.x, bu.y, bu.z, bu.w};
#pragma unroll
            for (int i = 0; i < 8; i++)
#pragma unroll
                for (int j = 0; j < 4; j++) {
                    accg[i][j] = fmaf(a[i], gb[j], accg[i][j]);
                    accu[i][j] = fmaf(a[i], ub[j], accu[i][j]);
                }
        }
        __syncthreads();
    }

    float* actBase = g_act + (size_t)e * T * I;
#pragma unroll
    for (int i = 0; i < 8; i++) {
        int slot = m0 + ty * 8 + i;
        if (slot >= cnt) continue;
        float* dst = actBase + (size_t)slot * I + n0 + tx * 4;
#pragma unroll
        for (int j = 0; j < 4; j++) {
            float g = accg[i][j];
            float sg = g / (1.f + expf(-g));   // silu
            dst[j] = sg * accu[i][j];
        }
    }
}

// ---------------- GEMM 2: out += w * (act @ Wd) ------------------------------
// SHARED_E=true: z==0, plain store (initializes out). false: z = expert id, atomicAdd.
template <bool SHARED_E>
__global__ void __launch_bounds__(256) gemm_down_kernel(
    const float* __restrict__ Wd_all, float* __restrict__ out) {
    const int ez = SHARED_E ? E : blockIdx.z;
    int cnt;
    const float* Wd;
    if (SHARED_E) {
        cnt = T;
        Wd = Wd_all;
    } else {
        cnt = g_counts[blockIdx.z];
        if ((int)blockIdx.y * 128 >= cnt) return;
        Wd = Wd_all + (size_t)blockIdx.z * I * H;
    }
    const float* act = g_act + (size_t)ez * T * I;

    __shared__ __align__(16) float As[8][128];
    __shared__ __align__(16) float Bs[8][64];

    const int tid = threadIdx.x;
    const int m0 = blockIdx.y * 128;
    const int n0 = blockIdx.x * 64;

    const int la_m = tid >> 1;
    const int la_k = (tid & 1) * 4;
    const int lb_k = tid >> 5;
    const int lb_n = (tid & 31) * 2;
    const int ty = tid >> 4;
    const int tx = tid & 15;

    const int slotA = m0 + la_m;
    const bool validA = slotA < cnt;

    float acc[8][4];
#pragma unroll
    for (int i = 0; i < 8; i++)
#pragma unroll
        for (int j = 0; j < 4; j++) acc[i][j] = 0.f;

    for (int k0 = 0; k0 < I; k0 += 8) {
        float4 av = make_float4(0.f, 0.f, 0.f, 0.f);
        if (validA)
            av = *reinterpret_cast<const float4*>(act + (size_t)slotA * I + k0 + la_k);
        As[la_k + 0][la_m] = av.x;
        As[la_k + 1][la_m] = av.y;
        As[la_k + 2][la_m] = av.z;
        As[la_k + 3][la_m] = av.w;

        float2 bv = *reinterpret_cast<const float2*>(Wd + (size_t)(k0 + lb_k) * H + n0 + lb_n);
        Bs[lb_k][lb_n]     = bv.x;
        Bs[lb_k][lb_n + 1] = bv.y;
        __syncthreads();

#pragma unroll
        for (int k = 0; k < 8; k++) {
            float4 a0 = *reinterpret_cast<const float4*>(&As[k][ty * 8]);
            float4 a1 = *reinterpret_cast<const float4*>(&As[k][ty * 8 + 4]);
            float4 bb = *reinterpret_cast<const float4*>(&Bs[k][tx * 4]);
            float a[8] = {a0.x, a0.y, a0.z, a0.w, a1.x, a1.y, a1.z, a1.w};
            float b[4] = {bb.x, bb.y, bb.z, bb.w};
#pragma unroll
            for (int i = 0; i < 8; i++)
#pragma unroll
                for (int j = 0; j < 4; j++)
                    acc[i][j] = fmaf(a[i], b[j], acc[i][j]);
        }
        __syncthreads();
    }

#pragma unroll
    for (int i = 0; i < 8; i++) {
        int slot = m0 + ty * 8 + i;
        if (slot >= cnt) continue;
        if (SHARED_E) {
            float* dst = out + (size_t)slot * H + n0 + tx * 4;
#pragma unroll
            for (int j = 0; j < 4; j++) dst[j] = acc[i][j];
        } else {
            int tok = g_list[blockIdx.z * T + slot];
            float w  = g_wlist[blockIdx.z * T + slot];
            float* dst = out + (size_t)tok * H + n0 + tx * 4;
#pragma unroll
            for (int j = 0; j < 4; j++) atomicAdd(&dst[j], w * acc[i][j]);
        }
    }
}

// ---------------- launch -----------------------------------------------------
extern "C" void kernel_launch(void* const* d_in, const int* in_sizes, int n_in,
                              void* d_out, int out_size) {
    const float* x   = (const float*)d_in[0];
    const float* rw  = (const float*)d_in[1];
    const float* gw  = (const float*)d_in[2];
    const float* uw  = (const float*)d_in[3];
    const float* dw  = (const float*)d_in[4];
    const float* sgw = (const float*)d_in[5];
    const float* suw = (const float*)d_in[6];
    const float* sdw = (const float*)d_in[7];
    float* out = (float*)d_out;

    init_kernel<<<1, 32>>>();
    router_kernel<<<T / 8, 256>>>(x, rw, out + (size_t)T * H + 2);
    finalize_kernel<<<1, 32>>>(out);

    // act = silu(X@Wg)*(X@Wu) for 8 routed experts + shared (z == E)
    gemm_gateup_kernel<<<dim3(I / 64, T / 128, E + 1), 256>>>(x, gw, uw, sgw, suw);

    // shared expert down-proj writes (initializes) out, then routed experts add
    gemm_down_kernel<true><<<dim3(H / 64, T / 128, 1), 256>>>(sdw, out);
    gemm_down_kernel<false><<<dim3(H / 64, T / 128, E), 256>>>(dw, out);
}

// round 3
// speedup vs baseline: 4.6025x; 4.6025x over previous
#include <cuda_runtime.h>
#include <cuda_bf16.h>
#include <math.h>
#include <stdint.h>

#define H 1024
#define I 2048
#define E 8
#define TOPK 2
#define T 4096   // B*S

// ======================= scratch (static device globals) =====================
__device__ __align__(256) int   g_counts[E];
__device__ __align__(256) float g_probsum[E];
__device__ float g_zsum;
__device__ __align__(256) int   g_list[E * T];
__device__ __align__(256) float g_wlist[E * T];

// bf16 hi/lo splits
__device__ __align__(256) __nv_bfloat16 g_xh[(size_t)T * H];
__device__ __align__(256) __nv_bfloat16 g_xl[(size_t)T * H];
__device__ __align__(256) __nv_bfloat16 g_gth[(size_t)E * I * H];   // gate^T [e][i][h]
__device__ __align__(256) __nv_bfloat16 g_gtl[(size_t)E * I * H];
__device__ __align__(256) __nv_bfloat16 g_uth[(size_t)E * I * H];   // up^T
__device__ __align__(256) __nv_bfloat16 g_utl[(size_t)E * I * H];
__device__ __align__(256) __nv_bfloat16 g_dth[(size_t)E * H * I];   // down^T [e][h][i]
__device__ __align__(256) __nv_bfloat16 g_dtl[(size_t)E * H * I];
__device__ __align__(256) __nv_bfloat16 g_sgth[(size_t)I * H];
__device__ __align__(256) __nv_bfloat16 g_sgtl[(size_t)I * H];
__device__ __align__(256) __nv_bfloat16 g_suth[(size_t)I * H];
__device__ __align__(256) __nv_bfloat16 g_sutl[(size_t)I * H];
__device__ __align__(256) __nv_bfloat16 g_sdth[(size_t)H * I];
__device__ __align__(256) __nv_bfloat16 g_sdtl[(size_t)H * I];
// activations (bf16 hi/lo), slot-major per expert; slot e==E is shared expert
__device__ __align__(256) __nv_bfloat16 g_acth[(size_t)(E + 1) * T * I];
__device__ __align__(256) __nv_bfloat16 g_actl[(size_t)(E + 1) * T * I];

// ======================= PTX helpers ========================================
static __device__ __forceinline__ uint32_t s2u(const void* p) {
    uint32_t a;
    asm("{ .reg .u64 t; cvta.to.shared.u64 t, %1; cvt.u32.u64 %0, t; }"
        : "=r"(a) : "l"(p));
    return a;
}
static __device__ __forceinline__ void ldsm_x4(uint32_t& r0, uint32_t& r1,
                                               uint32_t& r2, uint32_t& r3,
                                               uint32_t addr) {
    asm volatile("ldmatrix.sync.aligned.m8n8.x4.shared.b16 {%0,%1,%2,%3}, [%4];"
                 : "=r"(r0), "=r"(r1), "=r"(r2), "=r"(r3) : "r"(addr));
}
static __device__ __forceinline__ void ldsm_x2(uint32_t& r0, uint32_t& r1,
                                               uint32_t addr) {
    asm volatile("ldmatrix.sync.aligned.m8n8.x2.shared.b16 {%0,%1}, [%2];"
                 : "=r"(r0), "=r"(r1) : "r"(addr));
}
static __device__ __forceinline__ void mma_bf16(float* c, const uint32_t* a,
                                                uint32_t b0, uint32_t b1) {
    asm volatile(
        "mma.sync.aligned.m16n8k16.row.col.f32.bf16.bf16.f32 "
        "{%0,%1,%2,%3}, {%4,%5,%6,%7}, {%8,%9}, {%0,%1,%2,%3};"
        : "+f"(c[0]), "+f"(c[1]), "+f"(c[2]), "+f"(c[3])
        : "r"(a[0]), "r"(a[1]), "r"(a[2]), "r"(a[3]), "r"(b0), "r"(b1));
}
static __device__ __forceinline__ void cp16(uint32_t dst, const void* src,
                                            uint32_t sz) {
    asm volatile("cp.async.cg.shared.global [%0], [%1], 16, %2;"
                 :: "r"(dst), "l"(src), "r"(sz) : "memory");
}
#define CP_COMMIT() asm volatile("cp.async.commit_group;" ::: "memory")
#define CP_WAIT1()  asm volatile("cp.async.wait_group 1;" ::: "memory")
#define CP_WAIT0()  asm volatile("cp.async.wait_group 0;" ::: "memory")

#define SWZ(o) ((uint32_t)(o) ^ ((((uint32_t)(o)) >> 3) & 0x70u))

// ======================= SMEM layout ========================================
// gateup stage (64 KB): A_hi 16K | A_lo 16K | Bg_hi 8K | Bg_lo 8K | Bu_hi 8K | Bu_lo 8K
#define GU_STAGE  65536
#define GU_A_HI   0
#define GU_A_LO   16384
#define GU_BG_HI  32768
#define GU_BG_LO  40960
#define GU_BU_HI  49152
#define GU_BU_LO  57344
#define GU_SMEM   (1024 + 2 * GU_STAGE)
// down stage (48 KB): A_hi 16K | A_lo 16K | B_hi 8K | B_lo 8K
#define DN_STAGE  49152
#define DN_A_HI   0
#define DN_A_LO   16384
#define DN_B_HI   32768
#define DN_B_LO   40960
#define DN_SMEM   (1024 + 2 * DN_STAGE)

// ======================= small kernels ======================================
__global__ void init_kernel() {
    int i = threadIdx.x;
    if (i < E) { g_counts[i] = 0; g_probsum[i] = 0.f; }
    if (i == 0) g_zsum = 0.f;
}

__global__ void router_kernel(const float* __restrict__ x,
                              const float* __restrict__ rw,
                              float* __restrict__ out_logits) {
    int t = blockIdx.x * 8 + (threadIdx.x >> 5);
    int lane = threadIdx.x & 31;
    const float* xr = x + (size_t)t * H;

    float acc[E];
#pragma unroll
    for (int e = 0; e < E; e++) acc[e] = 0.f;
    for (int h = lane; h < H; h += 32) {
        float xv = xr[h];
        const float4* r4 = reinterpret_cast<const float4*>(rw + (size_t)h * E);
        float4 r0 = r4[0], r1 = r4[1];
        acc[0] += xv * r0.x; acc[1] += xv * r0.y;
        acc[2] += xv * r0.z; acc[3] += xv * r0.w;
        acc[4] += xv * r1.x; acc[5] += xv * r1.y;
        acc[6] += xv * r1.z; acc[7] += xv * r1.w;
    }
#pragma unroll
    for (int e = 0; e < E; e++)
#pragma unroll
        for (int off = 16; off > 0; off >>= 1)
            acc[e] += __shfl_xor_sync(0xffffffffu, acc[e], off);

    if (lane == 0) {
        float m = acc[0];
#pragma unroll
        for (int e = 1; e < E; e++) m = fmaxf(m, acc[e]);
        float p[E], s = 0.f;
#pragma unroll
        for (int e = 0; e < E; e++) { p[e] = expf(acc[e] - m); s += p[e]; }
        float inv = 1.f / s;
#pragma unroll
        for (int e = 0; e < E; e++) out_logits[(size_t)t * E + e] = acc[e];
        float lse = m + logf(s);
        atomicAdd(&g_zsum, lse * lse);
#pragma unroll
        for (int e = 0; e < E; e++) atomicAdd(&g_probsum[e], p[e] * inv);

        int e1 = 0;
#pragma unroll
        for (int e = 1; e < E; e++) if (acc[e] > acc[e1]) e1 = e;
        int e2 = (e1 == 0) ? 1 : 0;
#pragma unroll
        for (int e = 0; e < E; e++) if (e != e1 && acc[e] > acc[e2]) e2 = e;
        float p1 = p[e1] * inv, p2 = p[e2] * inv;
        float wn = 1.f / (p1 + p2);
        int pos1 = atomicAdd(&g_counts[e1], 1);
        g_list[e1 * T + pos1] = t;  g_wlist[e1 * T + pos1] = p1 * wn;
        int pos2 = atomicAdd(&g_counts[e2], 1);
        g_list[e2 * T + pos2] = t;  g_wlist[e2 * T + pos2] = p2 * wn;
    }
}

__global__ void finalize_kernel(float* __restrict__ out) {
    if (threadIdx.x == 0) {
        float aux = 0.f;
#pragma unroll
        for (int e = 0; e < E; e++) {
            float tpe = (float)g_counts[e] / (float)(TOPK * T);
            float ppe = g_probsum[e] / (float)T;
            aux += tpe * ppe;
        }
        out[(size_t)T * H]     = (float)E * aux;
        out[(size_t)T * H + 1] = g_zsum / (float)T;
    }
}

// x -> bf16 hi/lo
__global__ void convert_x_kernel(const float* __restrict__ x) {
    size_t i4 = (size_t)blockIdx.x * 256 + threadIdx.x;  // T*H/4 threads
    float4 v = reinterpret_cast<const float4*>(x)[i4];
    size_t o = i4 * 4;
    __nv_bfloat16 h0 = __float2bfloat16(v.x), h1 = __float2bfloat16(v.y);
    __nv_bfloat16 h2 = __float2bfloat16(v.z), h3 = __float2bfloat16(v.w);
    __nv_bfloat162 ha, hb, la, lb;
    ha.x = h0; ha.y = h1; hb.x = h2; hb.y = h3;
    la.x = __float2bfloat16(v.x - __bfloat162float(h0));
    la.y = __float2bfloat16(v.y - __bfloat162float(h1));
    lb.x = __float2bfloat16(v.z - __bfloat162float(h2));
    lb.y = __float2bfloat16(v.w - __bfloat162float(h3));
    reinterpret_cast<__nv_bfloat162*>(g_xh + o)[0] = ha;
    reinterpret_cast<__nv_bfloat162*>(g_xh + o)[1] = hb;
    reinterpret_cast<__nv_bfloat162*>(g_xl + o)[0] = la;
    reinterpret_cast<__nv_bfloat162*>(g_xl + o)[1] = lb;
}

// transpose [R][C] fp32 -> [C][R] bf16 hi/lo; 'which' selects destination
__global__ void transpose_split_kernel(const float* __restrict__ in, int which,
                                       int R, int C) {
    __shared__ float tile[32][33];
    __nv_bfloat16 *oh, *ol;
    size_t zoff = (size_t)blockIdx.z * R * C;
    switch (which) {
        case 0: oh = g_gth;  ol = g_gtl;  break;
        case 1: oh = g_uth;  ol = g_utl;  break;
        case 2: oh = g_dth;  ol = g_dtl;  break;
        case 3: oh = g_sgth; ol = g_sgtl; break;
        case 4: oh = g_suth; ol = g_sutl; break;
        default: oh = g_sdth; ol = g_sdtl; break;
    }
    const float* src = in + zoff;
    oh += zoff; ol += zoff;
    int c0 = blockIdx.x * 32, r0 = blockIdx.y * 32;
    int tx = threadIdx.x, ty = threadIdx.y;  // 32 x 8
#pragma unroll
    for (int i = 0; i < 4; i++)
        tile[ty + i * 8][tx] = src[(size_t)(r0 + ty + i * 8) * C + c0 + tx];
    __syncthreads();
#pragma unroll
    for (int i = 0; i < 4; i++) {
        float v = tile[tx][ty + i * 8];
        __nv_bfloat16 h = __float2bfloat16(v);
        size_t di = (size_t)(c0 + ty + i * 8) * R + r0 + tx;
        oh[di] = h;
        ol[di] = __float2bfloat16(v - __bfloat162float(h));
    }
}

// ======================= GEMM 1: gate+up (HMMA bf16x3) =======================
__global__ void __launch_bounds__(256, 1) mm_gateup_kernel() {
    extern __shared__ char smem[];
    const int e = blockIdx.z;
    const int cnt = (e < E) ? g_counts[e] : T;
    const int m0 = blockIdx.y * 128;
    if (m0 >= cnt) return;
    const int n0 = blockIdx.x * 64;
    const int tid = threadIdx.x;
    const int wid = tid >> 5;
    const int lane = tid & 31;

    int* rowTok = (int*)smem;
    if (tid < 128) {
        int slot = m0 + tid;
        rowTok[tid] = (slot < cnt) ? ((e < E) ? g_list[e * T + slot] : slot) : -1;
    }
    __syncthreads();

    const uint32_t sb = s2u(smem) + 1024;

    const __nv_bfloat16* Gh = (e < E) ? g_gth + (size_t)e * I * H : g_sgth;
    const __nv_bfloat16* Gl = (e < E) ? g_gtl + (size_t)e * I * H : g_sgtl;
    const __nv_bfloat16* Uh = (e < E) ? g_uth + (size_t)e * I * H : g_suth;
    const __nv_bfloat16* Ul = (e < E) ? g_utl + (size_t)e * I * H : g_sutl;

    const int u = tid & 7;
    const int rba = tid >> 3;

    auto load_stage = [&](int buf, int c) {
        const int k0 = c * 64;
        const uint32_t bp = sb + buf * GU_STAGE;
#pragma unroll
        for (int rr = 0; rr < 4; rr++) {
            int row = rba + rr * 32;
            int tok = rowTok[row];
            uint32_t d = SWZ(row * 128 + u * 16);
            size_t go = (size_t)(tok >= 0 ? tok : 0) * H + k0 + u * 8;
            uint32_t szv = (tok >= 0) ? 16u : 0u;
            cp16(bp + GU_A_HI + d, g_xh + go, szv);
            cp16(bp + GU_A_LO + d, g_xl + go, szv);
        }
#pragma unroll
        for (int rr = 0; rr < 2; rr++) {
            int row = rba + rr * 32;
            uint32_t d = SWZ(row * 128 + u * 16);
            size_t go = (size_t)(n0 + row) * H + k0 + u * 8;
            cp16(bp + GU_BG_HI + d, Gh + go, 16);
            cp16(bp + GU_BG_LO + d, Gl + go, 16);
            cp16(bp + GU_BU_HI + d, Uh + go, 16);
            cp16(bp + GU_BU_LO + d, Ul + go, 16);
        }
    };

    float accG[4][2][4], accU[4][2][4];
#pragma unroll
    for (int i = 0; i < 4; i++)
#pragma unroll
        for (int j = 0; j < 2; j++)
#pragma unroll
            for (int q = 0; q < 4; q++) { accG[i][j][q] = 0.f; accU[i][j][q] = 0.f; }

    const int mw = (wid & 1) * 64;
    const int nw = (wid >> 1) * 16;
    const int al7 = lane & 7;
    const int arow_off = ((lane >> 3) & 1) * 8 + al7;
    const int akb_off = (lane >> 4) * 16;
    const int bkb_off = ((lane >> 3) & 1) * 16;

    auto compute_stage = [&](int buf) {
        const uint32_t bp = sb + buf * GU_STAGE;
#pragma unroll
        for (int kk = 0; kk < 4; kk++) {
            uint32_t ah[4][4], al[4][4];
            int kb = kk * 32;
#pragma unroll
            for (int i = 0; i < 4; i++) {
                int row = mw + i * 16 + arow_off;
                uint32_t ao = SWZ(row * 128 + kb + akb_off);
                ldsm_x4(ah[i][0], ah[i][1], ah[i][2], ah[i][3], bp + GU_A_HI + ao);
                ldsm_x4(al[i][0], al[i][1], al[i][2], al[i][3], bp + GU_A_LO + ao);
            }
#pragma unroll
            for (int j = 0; j < 2; j++) {
                int brow = nw + j * 8 + al7;
                uint32_t bo = SWZ(brow * 128 + kb + bkb_off);
                uint32_t gh0, gh1, gl0, gl1, uh0, uh1, ul0, ul1;
                ldsm_x2(gh0, gh1, bp + GU_BG_HI + bo);
                ldsm_x2(gl0, gl1, bp + GU_BG_LO + bo);
                ldsm_x2(uh0, uh1, bp + GU_BU_HI + bo);
                ldsm_x2(ul0, ul1, bp + GU_BU_LO + bo);
#pragma unroll
                for (int i = 0; i < 4; i++) {
                    mma_bf16(accG[i][j], ah[i], gh0, gh1);
                    mma_bf16(accG[i][j], ah[i], gl0, gl1);
                    mma_bf16(accG[i][j], al[i], gh0, gh1);
                    mma_bf16(accU[i][j], ah[i], uh0, uh1);
                    mma_bf16(accU[i][j], ah[i], ul0, ul1);
                    mma_bf16(accU[i][j], al[i], uh0, uh1);
                }
            }
        }
    };

    load_stage(0, 0); CP_COMMIT();
    load_stage(1, 1); CP_COMMIT();
    const int NC = H / 64;  // 16
    for (int c = 0; c < NC; c++) {
        if (c < NC - 1) CP_WAIT1(); else CP_WAIT0();
        __syncthreads();
        compute_stage(c & 1);
        if (c + 2 < NC) { __syncthreads(); load_stage(c & 1, c + 2); CP_COMMIT(); }
    }

    // epilogue: silu(gate)*up -> bf16 hi/lo act
    const int r4 = lane >> 2;
    const int cp2 = (lane & 3) * 2;
#pragma unroll
    for (int i = 0; i < 4; i++)
#pragma unroll
        for (int hh = 0; hh < 2; hh++) {
            int slot = m0 + mw + i * 16 + r4 + hh * 8;
            if (slot >= cnt) continue;
#pragma unroll
            for (int j = 0; j < 2; j++) {
                float g0 = accG[i][j][hh * 2 + 0], g1 = accG[i][j][hh * 2 + 1];
                float u0 = accU[i][j][hh * 2 + 0], u1 = accU[i][j][hh * 2 + 1];
                float v0 = g0 / (1.f + __expf(-g0)) * u0;
                float v1 = g1 / (1.f + __expf(-g1)) * u1;
                __nv_bfloat16 h0 = __float2bfloat16(v0), h1 = __float2bfloat16(v1);
                __nv_bfloat162 hp; hp.x = h0; hp.y = h1;
                __nv_bfloat162 lp;
                lp.x = __float2bfloat16(v0 - __bfloat162float(h0));
                lp.y = __float2bfloat16(v1 - __bfloat162float(h1));
                size_t ai = (size_t)e * T * I + (size_t)slot * I + n0 + nw + j * 8 + cp2;
                *reinterpret_cast<__nv_bfloat162*>(g_acth + ai) = hp;
                *reinterpret_cast<__nv_bfloat162*>(g_actl + ai) = lp;
            }
        }
}

// ======================= GEMM 2: down (HMMA bf16x3) ==========================
template <bool SHARED_E>
__global__ void __launch_bounds__(256) mm_down_kernel(float* __restrict__ out) {
    extern __shared__ char smem[];
    const int e  = SHARED_E ? 0 : blockIdx.z;
    const int ea = SHARED_E ? E : blockIdx.z;
    const int cnt = SHARED_E ? T : g_counts[e];
    const int m0 = blockIdx.y * 128;
    if (m0 >= cnt) return;
    const int n0 = blockIdx.x * 64;
    const int tid = threadIdx.x;
    const int wid = tid >> 5;
    const int lane = tid & 31;

    int* tokSm = (int*)smem;
    float* wSm = (float*)(smem + 512);
    if (!SHARED_E && tid < 128) {
        int slot = m0 + tid;
        tokSm[tid] = (slot < cnt) ? g_list[e * T + slot] : 0;
        wSm[tid]   = (slot < cnt) ? g_wlist[e * T + slot] : 0.f;
    }
    __syncthreads();

    const uint32_t sb = s2u(smem) + 1024;

    const __nv_bfloat16* Bh = SHARED_E ? g_sdth : g_dth + (size_t)e * H * I;
    const __nv_bfloat16* Bl = SHARED_E ? g_sdtl : g_dtl + (size_t)e * H * I;
    const __nv_bfloat16* Ah = g_acth + (size_t)ea * T * I;
    const __nv_bfloat16* Al = g_actl + (size_t)ea * T * I;

    const int u = tid & 7;
    const int rba = tid >> 3;

    auto load_stage = [&](int buf, int c) {
        const int k0 = c * 64;
        const uint32_t bp = sb + buf * DN_STAGE;
#pragma unroll
        for (int rr = 0; rr < 4; rr++) {
            int row = rba + rr * 32;
            int slot = m0 + row;
            uint32_t d = SWZ(row * 128 + u * 16);
            size_t go = (size_t)(slot < cnt ? slot : 0) * I + k0 + u * 8;
            uint32_t szv = (slot < cnt) ? 16u : 0u;
            cp16(bp + DN_A_HI + d, Ah + go, szv);
            cp16(bp + DN_A_LO + d, Al + go, szv);
        }
#pragma unroll
        for (int rr = 0; rr < 2; rr++) {
            int row = rba + rr * 32;
            uint32_t d = SWZ(row * 128 + u * 16);
            size_t go = (size_t)(n0 + row) * I + k0 + u * 8;
            cp16(bp + DN_B_HI + d, Bh + go, 16);
            cp16(bp + DN_B_LO + d, Bl + go, 16);
        }
    };

    float acc[4][2][4];
#pragma unroll
    for (int i = 0; i < 4; i++)
#pragma unroll
        for (int j = 0; j < 2; j++)
#pragma unroll
            for (int q = 0; q < 4; q++) acc[i][j][q] = 0.f;

    const int mw = (wid & 1) * 64;
    const int nw = (wid >> 1) * 16;
    const int al7 = lane & 7;
    const int arow_off = ((lane >> 3) & 1) * 8 + al7;
    const int akb_off = (lane >> 4) * 16;
    const int bkb_off = ((lane >> 3) & 1) * 16;

    auto compute_stage = [&](int buf) {
        const uint32_t bp = sb + buf * DN_STAGE;
#pragma unroll
        for (int kk = 0; kk < 4; kk++) {
            uint32_t ah[4][4], al[4][4];
            int kb = kk * 32;
#pragma unroll
            for (int i = 0; i < 4; i++) {
                int row = mw + i * 16 + arow_off;
                uint32_t ao = SWZ(row * 128 + kb + akb_off);
                ldsm_x4(ah[i][0], ah[i][1], ah[i][2], ah[i][3], bp + DN_A_HI + ao);
                ldsm_x4(al[i][0], al[i][1], al[i][2], al[i][3], bp + DN_A_LO + ao);
            }
#pragma unroll
            for (int j = 0; j < 2; j++) {
                int brow = nw + j * 8 + al7;
                uint32_t bo = SWZ(brow * 128 + kb + bkb_off);
                uint32_t bh0, bh1, bl0, bl1;
                ldsm_x2(bh0, bh1, bp + DN_B_HI + bo);
                ldsm_x2(bl0, bl1, bp + DN_B_LO + bo);
#pragma unroll
                for (int i = 0; i < 4; i++) {
                    mma_bf16(acc[i][j], ah[i], bh0, bh1);
                    mma_bf16(acc[i][j], ah[i], bl0, bl1);
                    mma_bf16(acc[i][j], al[i], bh0, bh1);
                }
            }
        }
    };

    load_stage(0, 0); CP_COMMIT();
    load_stage(1, 1); CP_COMMIT();
    const int NC = I / 64;  // 32
    for (int c = 0; c < NC; c++) {
        if (c < NC - 1) CP_WAIT1(); else CP_WAIT0();
        __syncthreads();
        compute_stage(c & 1);
        if (c + 2 < NC) { __syncthreads(); load_stage(c & 1, c + 2); CP_COMMIT(); }
    }

    const int r4 = lane >> 2;
    const int cp2 = (lane & 3) * 2;
#pragma unroll
    for (int i = 0; i < 4; i++)
#pragma unroll
        for (int hh = 0; hh < 2; hh++) {
            int row = mw + i * 16 + r4 + hh * 8;
            int slot = m0 + row;
            if (slot >= cnt) continue;
#pragma unroll
            for (int j = 0; j < 2; j++) {
                float v0 = acc[i][j][hh * 2 + 0];
                float v1 = acc[i][j][hh * 2 + 1];
                int col = n0 + nw + j * 8 + cp2;
                if (SHARED_E) {
                    float2* dst = reinterpret_cast<float2*>(out + (size_t)slot * H + col);
                    *dst = make_float2(v0, v1);
                } else {
                    int tok = tokSm[row];
                    float w = wSm[row];
                    float* dst = out + (size_t)tok * H + col;
                    atomicAdd(&dst[0], w * v0);
                    atomicAdd(&dst[1], w * v1);
                }
            }
        }
}

// ======================= launch =============================================
extern "C" void kernel_launch(void* const* d_in, const int* in_sizes, int n_in,
                              void* d_out, int out_size) {
    const float* x   = (const float*)d_in[0];
    const float* rw  = (const float*)d_in[1];
    const float* gw  = (const float*)d_in[2];
    const float* uw  = (const float*)d_in[3];
    const float* dw  = (const float*)d_in[4];
    const float* sgw = (const float*)d_in[5];
    const float* suw = (const float*)d_in[6];
    const float* sdw = (const float*)d_in[7];
    float* out = (float*)d_out;

    cudaFuncSetAttribute(mm_gateup_kernel,
                         cudaFuncAttributeMaxDynamicSharedMemorySize, GU_SMEM);
    cudaFuncSetAttribute(mm_down_kernel<true>,
                         cudaFuncAttributeMaxDynamicSharedMemorySize, DN_SMEM);
    cudaFuncSetAttribute(mm_down_kernel<false>,
                         cudaFuncAttributeMaxDynamicSharedMemorySize, DN_SMEM);

    init_kernel<<<1, 32>>>();
    router_kernel<<<T / 8, 256>>>(x, rw, out + (size_t)T * H + 2);
    finalize_kernel<<<1, 32>>>(out);

    convert_x_kernel<<<(T * H / 4) / 256, 256>>>(x);
    dim3 tb(32, 8);
    transpose_split_kernel<<<dim3(I / 32, H / 32, E), tb>>>(gw, 0, H, I);
    transpose_split_kernel<<<dim3(I / 32, H / 32, E), tb>>>(uw, 1, H, I);
    transpose_split_kernel<<<dim3(H / 32, I / 32, E), tb>>>(dw, 2, I, H);
    transpose_split_kernel<<<dim3(I / 32, H / 32, 1), tb>>>(sgw, 3, H, I);
    transpose_split_kernel<<<dim3(I / 32, H / 32, 1), tb>>>(suw, 4, H, I);
    transpose_split_kernel<<<dim3(H / 32, I / 32, 1), tb>>>(sdw, 5, I, H);

    mm_gateup_kernel<<<dim3(I / 64, T / 128, E + 1), 256, GU_SMEM>>>();
    mm_down_kernel<true><<<dim3(H / 64, T / 128, 1), 256, DN_SMEM>>>(out);
    mm_down_kernel<false><<<dim3(H / 64, T / 128, E), 256, DN_SMEM>>>(out);
}